// round 4
// baseline (speedup 1.0000x reference)
#include <cuda_runtime.h>
#include <cuda_bf16.h>
#include <math.h>
#include <stdint.h>

// ---------------- problem constants ----------------
#define BATCH   8
#define T       8192
#define IN_F    128
#define OUT_F   128
#define NSTATE  256
#define NC      64
#define CHUNK   128
#define MROWS   (BATCH * T)     // 65536
#define SCOLS   512             // 2*NSTATE, INTERLEAVED: col 2n=re_n, 2n+1=im_n
#define KOUT    640             // 512 states + 128 x

// ---------------- scratch (device globals) ----------------
__device__ __align__(256) float         g_S[(size_t)MROWS * SCOLS];   // Bu fp32 (interleaved)
__device__ __align__(256) __nv_bfloat16 g_Sh[(size_t)MROWS * SCOLS];  // states hi (interleaved)
__device__ __align__(256) __nv_bfloat16 g_Sl[(size_t)MROWS * SCOLS];  // states lo
__device__ __align__(256) __nv_bfloat16 g_xh[(size_t)MROWS * IN_F];
__device__ __align__(256) __nv_bfloat16 g_xl[(size_t)MROWS * IN_F];
__device__ __align__(256) __nv_bfloat16 g_W1h[SCOLS * IN_F];          // interleaved rows
__device__ __align__(256) __nv_bfloat16 g_W1l[SCOLS * IN_F];
__device__ __align__(256) __nv_bfloat16 g_Woh[OUT_F * KOUT];          // interleaved cols (k<512)
__device__ __align__(256) __nv_bfloat16 g_Wol[OUT_F * KOUT];
__device__ float   g_carry[BATCH * NC * NSTATE * 2];
__device__ float2  g_lam[NSTATE];
__device__ float2  g_lam32[NSTATE];    // Lambda^32
__device__ double2 g_lamL[NSTATE];     // Lambda^128 (fp64)

// ---------------- PTX helpers ----------------
__device__ __forceinline__ uint32_t smem_u32(const void* p) {
    uint32_t a;
    asm("{ .reg .u64 t; cvta.to.shared.u64 t, %1; cvt.u32.u64 %0, t; }" : "=r"(a) : "l"(p));
    return a;
}
__device__ __forceinline__ void cp16(uint32_t smem, const void* g) {
    asm volatile("cp.async.cg.shared.global [%0], [%1], 16;" :: "r"(smem), "l"(g));
}
#define CP_COMMIT() asm volatile("cp.async.commit_group;" ::: "memory")
template <int N>
__device__ __forceinline__ void cp_wait() {
    asm volatile("cp.async.wait_group %0;" :: "n"(N) : "memory");
}
__device__ __forceinline__ void ldsm4(uint32_t* r, uint32_t addr) {
    asm volatile("ldmatrix.sync.aligned.m8n8.x4.shared.b16 {%0,%1,%2,%3}, [%4];"
                 : "=r"(r[0]), "=r"(r[1]), "=r"(r[2]), "=r"(r[3]) : "r"(addr));
}
__device__ __forceinline__ void mma_bf16(float* c, const uint32_t* a, const uint32_t* b) {
    asm volatile("mma.sync.aligned.m16n8k16.row.col.f32.bf16.bf16.f32 "
                 "{%0,%1,%2,%3}, {%4,%5,%6,%7}, {%8,%9}, {%0,%1,%2,%3};"
                 : "+f"(c[0]), "+f"(c[1]), "+f"(c[2]), "+f"(c[3])
                 : "r"(a[0]), "r"(a[1]), "r"(a[2]), "r"(a[3]), "r"(b[0]), "r"(b[1]));
}

// ---------------- prep ----------------
__device__ __forceinline__ void split_bf16(float v, __nv_bfloat16& h, __nv_bfloat16& l) {
    h = __float2bfloat16(v);
    l = __float2bfloat16(v - __bfloat162float(h));
}

__global__ void prep_lambda_kernel(const float* __restrict__ nu_log,
                                   const float* __restrict__ theta_log) {
    int n = threadIdx.x;
    double nu  = exp((double)nu_log[n]);
    double th  = exp((double)theta_log[n]);
    double mod = exp(-nu);
    g_lam[n] = make_float2((float)(mod * cos(th)), (float)(mod * sin(th)));
    double m32 = exp(-32.0 * nu);
    g_lam32[n] = make_float2((float)(m32 * cos(32.0 * th)), (float)(m32 * sin(32.0 * th)));
    double mL = exp(-(double)CHUNK * nu);
    double pL = (double)CHUNK * th;
    g_lamL[n] = make_double2(mL * cos(pL), mL * sin(pL));
}

__global__ void prep_w1_kernel(const float* __restrict__ gamma_log,
                               const float* __restrict__ B_re,
                               const float* __restrict__ B_im) {
    int idx = blockIdx.x * blockDim.x + threadIdx.x;
    if (idx >= SCOLS * IN_F) return;
    int r = idx / IN_F, i = idx % IN_F;
    int s = r >> 1;
    float gam = expf(gamma_log[s]);
    float v = gam * ((r & 1) ? B_im[s * IN_F + i] : B_re[s * IN_F + i]);
    split_bf16(v, g_W1h[idx], g_W1l[idx]);
}

__global__ void prep_wout_kernel(const float* __restrict__ C_re,
                                 const float* __restrict__ C_im,
                                 const float* __restrict__ D) {
    int idx = blockIdx.x * blockDim.x + threadIdx.x;
    if (idx >= OUT_F * KOUT) return;
    int o = idx / KOUT, k = idx % KOUT;
    float v;
    if (k < 512) {
        int s = k >> 1;
        v = (k & 1) ? -C_im[o * NSTATE + s] : C_re[o * NSTATE + s];
    } else {
        v = D[o * IN_F + (k - 512)];
    }
    split_bf16(v, g_Woh[idx], g_Wol[idx]);
}

__global__ void convert_x_kernel(const float* __restrict__ x) {
    size_t i = ((size_t)blockIdx.x * blockDim.x + threadIdx.x) * 4;
    float4 v = *(const float4*)(x + i);
    __nv_bfloat16 h0, l0, h1, l1, h2, l2, h3, l3;
    split_bf16(v.x, h0, l0); split_bf16(v.y, h1, l1);
    split_bf16(v.z, h2, l2); split_bf16(v.w, h3, l3);
    __nv_bfloat162* ph = (__nv_bfloat162*)(g_xh + i);
    __nv_bfloat162* pl = (__nv_bfloat162*)(g_xl + i);
    ph[0] = __nv_bfloat162(h0, h1); ph[1] = __nv_bfloat162(h2, h3);
    pl[0] = __nv_bfloat162(l0, l1); pl[1] = __nv_bfloat162(l2, l3);
}

// ---------------- MMA GEMM ----------------
// Block 128x128, 16 warps of 32x32, K-chunk 32, 2-stage cp.async double buffer.
// smem tile: 128 rows x 32 bf16, row stride 80B (conflict-free ldmatrix).
#define ROW_B   80
#define TILE_B  (128 * ROW_B)          // 10240
#define STAGE_B (4 * TILE_B)           // Ah, Al, Bh, Bl
#define GSMEM   (2 * STAGE_B)          // 81920

__device__ __forceinline__ void load_tile(uint32_t sm, const __nv_bfloat16* __restrict__ g,
                                          size_t row0, int ld, int kb, int tid) {
    int r = tid >> 2, c = tid & 3;     // 512 threads = 512 x 16B
    cp16(sm + r * ROW_B + c * 16, g + (row0 + r) * (size_t)ld + kb + c * 8);
}

__global__ void __launch_bounds__(512, 1) gemm_mma_kernel(
    const __nv_bfloat16* __restrict__ Ah0, const __nv_bfloat16* __restrict__ Al0,
    int lda0, int nk0,
    const __nv_bfloat16* __restrict__ Ah1, const __nv_bfloat16* __restrict__ Al1,
    int lda1,
    const __nv_bfloat16* __restrict__ Bh, const __nv_bfloat16* __restrict__ Bl,
    int ldb, float* __restrict__ out, int ldo, int nk, int do_scan)
{
    extern __shared__ char smem[];
    uint32_t sb = smem_u32(smem);
    int tid = threadIdx.x, lane = tid & 31, wid = tid >> 5;
    int wm = wid & 3, wn = wid >> 2;           // 4x4 warp grid
    size_t m0 = (size_t)blockIdx.x * 128;
    int n0 = blockIdx.y * 128;

    float acc[2][4][4];
    #pragma unroll
    for (int a = 0; a < 2; a++)
        #pragma unroll
        for (int b = 0; b < 4; b++)
            #pragma unroll
            for (int c = 0; c < 4; c++) acc[a][b][c] = 0.f;

    auto load_chunk = [&](int i, int s) {
        uint32_t st = sb + s * STAGE_B;
        const __nv_bfloat16 *ah, *al;
        int lda, kb;
        if (i < nk0) { ah = Ah0; al = Al0; lda = lda0; kb = i * 32; }
        else         { ah = Ah1; al = Al1; lda = lda1; kb = (i - nk0) * 32; }
        load_tile(st,              ah, m0, lda, kb, tid);
        load_tile(st + TILE_B,     al, m0, lda, kb, tid);
        load_tile(st + 2 * TILE_B, Bh, (size_t)n0, ldb, i * 32, tid);
        load_tile(st + 3 * TILE_B, Bl, (size_t)n0, ldb, i * 32, tid);
    };

    load_chunk(0, 0);
    CP_COMMIT();

    for (int i = 0; i < nk; i++) {
        if (i + 1 < nk) { load_chunk(i + 1, (i + 1) & 1); CP_COMMIT(); cp_wait<1>(); }
        else            { cp_wait<0>(); }
        __syncthreads();

        uint32_t st = sb + (i & 1) * STAGE_B;
        #pragma unroll
        for (int kk = 0; kk < 32; kk += 16) {
            uint32_t ah[2][4], al[2][4], bh[2][4], bl[2][4];
            int arow = wm * 32 + (lane & 15);
            int acol = kk + ((lane >> 4) << 3);
            #pragma unroll
            for (int mi = 0; mi < 2; mi++) {
                uint32_t ad = st + (arow + mi * 16) * ROW_B + acol * 2;
                ldsm4(ah[mi], ad);
                ldsm4(al[mi], ad + TILE_B);
            }
            int brow = wn * 32 + ((lane >> 4) << 3) + (lane & 7);
            int bcol = kk + (((lane >> 3) & 1) << 3);
            #pragma unroll
            for (int g = 0; g < 2; g++) {
                uint32_t bd = st + 2 * TILE_B + (brow + g * 16) * ROW_B + bcol * 2;
                ldsm4(bh[g], bd);
                ldsm4(bl[g], bd + TILE_B);
            }
            #pragma unroll
            for (int mi = 0; mi < 2; mi++)
                #pragma unroll
                for (int ni = 0; ni < 4; ni++) {
                    const uint32_t* pbh = &bh[ni >> 1][(ni & 1) * 2];
                    const uint32_t* pbl = &bl[ni >> 1][(ni & 1) * 2];
                    mma_bf16(acc[mi][ni], ah[mi], pbh);
                    mma_bf16(acc[mi][ni], ah[mi], pbl);
                    mma_bf16(acc[mi][ni], al[mi], pbh);
                }
        }
        __syncthreads();
    }

    // ---- epilogue ----
    float* smf = (float*)smem;   // 128x128 fp32 staging (64KB) for fused carry scan
    int r0 = wm * 32 + (lane >> 2);
    int c0 = wn * 32 + (lane & 3) * 2;
    #pragma unroll
    for (int mi = 0; mi < 2; mi++)
        #pragma unroll
        for (int ni = 0; ni < 4; ni++) {
            int rl = r0 + mi * 16;
            int cl = c0 + ni * 8;
            float2 v01 = make_float2(acc[mi][ni][0], acc[mi][ni][1]);
            float2 v23 = make_float2(acc[mi][ni][2], acc[mi][ni][3]);
            *(float2*)(out + (m0 + rl) * (size_t)ldo + n0 + cl)     = v01;
            *(float2*)(out + (m0 + rl + 8) * (size_t)ldo + n0 + cl) = v23;
            if (do_scan) {
                *(float2*)(smf + rl * 128 + cl)       = v01;
                *(float2*)(smf + (rl + 8) * 128 + cl) = v23;
            }
        }

    if (do_scan) {
        // fused local-carry scan over this (batch,chunk) tile's 64 complex states
        float2* segc = (float2*)(smf + 128 * 128);   // 4 x 64 segment carries
        int sbase = (n0 >> 1);                        // first global state in tile
        __syncthreads();
        if (tid < 256) {
            int seg = tid >> 6, s = tid & 63;
            float2 lam = g_lam[sbase + s];
            float re = 0.f, im = 0.f;
            const float* col = smf + 2 * s;
            #pragma unroll 4
            for (int j = seg * 32; j < seg * 32 + 32; j++) {
                float2 v = *(const float2*)(col + j * 128);
                float nre = fmaf(lam.x, re, fmaf(-lam.y, im, v.x));
                float nim = fmaf(lam.x, im, fmaf( lam.y, re, v.y));
                re = nre; im = nim;
            }
            segc[seg * 64 + s] = make_float2(re, im);
        }
        __syncthreads();
        if (tid < 64) {
            int s = tid;
            float2 l32 = g_lam32[sbase + s];
            float2 c = segc[s];
            #pragma unroll
            for (int seg = 1; seg < 4; seg++) {
                float2 d = segc[seg * 64 + s];
                float nre = fmaf(l32.x, c.x, fmaf(-l32.y, c.y, d.x));
                float nim = fmaf(l32.x, c.y, fmaf( l32.y, c.x, d.y));
                c = make_float2(nre, nim);
            }
            int bx = blockIdx.x;
            int b = bx >> 6, ch = bx & 63;
            size_t idx = (((size_t)b * NC + ch) * NSTATE + sbase + s) * 2;
            g_carry[idx]     = c.x;
            g_carry[idx + 1] = c.y;
        }
    }
}

// ---------------- cross-chunk combine (fp64) ----------------
__global__ void combine_kernel() {
    int b = blockIdx.x;
    int n = threadIdx.x;
    double2 lL = g_lamL[n];
    double pre = 0.0, pim = 0.0;
    for (int c = 0; c < NC; c++) {
        size_t idx = (((size_t)b * NC + c) * NSTATE + n) * 2;
        double cre = (double)g_carry[idx];
        double cim = (double)g_carry[idx + 1];
        double nre = lL.x * pre - lL.y * pim + cre;
        double nim = lL.x * pim + lL.y * pre + cim;
        pre = nre; pim = nim;
        g_carry[idx]     = (float)pre;
        g_carry[idx + 1] = (float)pim;
    }
}

// ---------------- final scan: states -> bf16 hi/lo (interleaved) ----------------
__global__ void scan_final_kernel() {
    int b = blockIdx.x >> 6;
    int c = blockIdx.x & 63;
    int n = threadIdx.x;          // state
    float2 lam = g_lam[n];
    float sre = 0.f, sim = 0.f;
    if (c > 0) {
        size_t pidx = (((size_t)b * NC + (c - 1)) * NSTATE + n) * 2;
        sre = g_carry[pidx];
        sim = g_carry[pidx + 1];
    }
    size_t rbase = (size_t)(b * T + c * CHUNK);
    const float2* base = (const float2*)(g_S + rbase * SCOLS) + n;
    __nv_bfloat162* oh = (__nv_bfloat162*)(g_Sh + rbase * SCOLS) + n;
    __nv_bfloat162* ol = (__nv_bfloat162*)(g_Sl + rbase * SCOLS) + n;
    #pragma unroll 2
    for (int j = 0; j < CHUNK; j++) {
        float2 v = base[(size_t)j * (SCOLS / 2)];
        float nre = fmaf(lam.x, sre, fmaf(-lam.y, sim, v.x));
        float nim = fmaf(lam.x, sim, fmaf( lam.y, sre, v.y));
        sre = nre; sim = nim;
        __nv_bfloat16 hr, lr, hi, li;
        split_bf16(nre, hr, lr);
        split_bf16(nim, hi, li);
        oh[(size_t)j * (SCOLS / 2)] = __nv_bfloat162(hr, hi);
        ol[(size_t)j * (SCOLS / 2)] = __nv_bfloat162(lr, li);
    }
}

// ---------------- launch ----------------
extern "C" void kernel_launch(void* const* d_in, const int* in_sizes, int n_in,
                              void* d_out, int out_size) {
    const float* x         = (const float*)d_in[0];
    const float* nu_log    = (const float*)d_in[1];
    const float* theta_log = (const float*)d_in[2];
    const float* gamma_log = (const float*)d_in[3];
    const float* B_re      = (const float*)d_in[4];
    const float* B_im      = (const float*)d_in[5];
    const float* C_re      = (const float*)d_in[6];
    const float* C_im      = (const float*)d_in[7];
    const float* D         = (const float*)d_in[8];
    float* out = (float*)d_out;

    __nv_bfloat16 *xh, *xl, *w1h, *w1l, *sh, *sl, *woh, *wol;
    float* S;
    cudaGetSymbolAddress((void**)&xh,  g_xh);
    cudaGetSymbolAddress((void**)&xl,  g_xl);
    cudaGetSymbolAddress((void**)&w1h, g_W1h);
    cudaGetSymbolAddress((void**)&w1l, g_W1l);
    cudaGetSymbolAddress((void**)&sh,  g_Sh);
    cudaGetSymbolAddress((void**)&sl,  g_Sl);
    cudaGetSymbolAddress((void**)&woh, g_Woh);
    cudaGetSymbolAddress((void**)&wol, g_Wol);
    cudaGetSymbolAddress((void**)&S,   g_S);

    cudaFuncSetAttribute(gemm_mma_kernel, cudaFuncAttributeMaxDynamicSharedMemorySize, GSMEM);

    prep_lambda_kernel<<<1, 256>>>(nu_log, theta_log);
    prep_w1_kernel<<<(SCOLS * IN_F + 255) / 256, 256>>>(gamma_log, B_re, B_im);
    prep_wout_kernel<<<(OUT_F * KOUT + 255) / 256, 256>>>(C_re, C_im, D);
    convert_x_kernel<<<(MROWS * IN_F / 4) / 256, 256>>>(x);

    // GEMM1: Bu = x @ W1^T  [65536 x 512], K=128, fused local-carry scan
    gemm_mma_kernel<<<dim3(MROWS / 128, SCOLS / 128), 512, GSMEM>>>(
        xh, xl, IN_F, 4, xh, xl, IN_F, w1h, w1l, IN_F, S, SCOLS, 4, 1);

    combine_kernel<<<BATCH, NSTATE>>>();
    scan_final_kernel<<<BATCH * NC, NSTATE>>>();

    // GEMM2: out = S @ Wout^T (K 0..511 states interleaved, 512..639 x)
    gemm_mma_kernel<<<dim3(MROWS / 128, 1), 512, GSMEM>>>(
        sh, sl, SCOLS, 16, xh, xl, IN_F, woh, wol, KOUT, out, OUT_F, 20, 0);
}